// round 2
// baseline (speedup 1.0000x reference)
#include <cuda_runtime.h>
#include <math.h>

#define N_ACT 4096
#define N_KEY 4096
#define DMODEL 512
#define NHEAD 4
#define DKH 128
#define NEGV (-1e9f)

#define BN 32
#define BM 32
#define LDQ 516
#define LDSS 33

// scratch (static device allocations — allowed)
__device__ float g_q[N_ACT * DMODEL];
__device__ float g_k[N_KEY * DMODEL];
__device__ float g_v[N_KEY * DMODEL];
__device__ float g_ctx[N_ACT * DMODEL];
__device__ float g_wt[DKH * DMODEL];
__device__ float g_bt[DKH];
__device__ int   g_valid[N_ACT];
__device__ unsigned char g_mask[N_ACT * N_KEY];
__device__ int   g_mflag;   // 0 = bool bytes, 1 = int32, 2 = float32

__device__ __forceinline__ float nanfix(float x) {
    if (isnan(x)) return 0.f;
    if (isinf(x)) return x > 0.f ? 1.f : -1.f;
    return x;
}

// Fast exp for x <= 0, FFMA-only (no MUFU). ~2e-6 rel error.
__device__ __forceinline__ float fexp(float x) {
    x = fminf(x, 0.f);
    x = fmaxf(x, -87.0f);
    const float LOG2E = 1.4426950408889634f;
    float t = fmaf(x, LOG2E, 12582912.f);   // round-to-nearest via magic number
    float jf = t - 12582912.f;
    int ji = (__float_as_int(t) & 0x7FFFFF) - 0x400000;
    float r = fmaf(x, LOG2E, -jf);          // in [-0.5, 0.5]
    float g = r * 0.6931471805599453f;
    float p = fmaf(g, 0.0083333333f, 0.0416666666f);
    p = fmaf(p, g, 0.1666666666f);
    p = fmaf(p, g, 0.5f);
    p = fmaf(p, g, 1.0f);
    p = fmaf(p, g, 1.0f);
    return __int_as_float((ji + 127) << 23) * p;
}

// ---------------------------------------------------------------------------
// Mask dtype detection: inspect first 16384 32-bit words.
//   float32 mask: words are 0x00000000 or 0x3F800000
//   bool mask   : bytes are 0/1 -> many words have nonzero bytes above byte0
//   int32 mask  : words are 0 or 1 (upper 3 bytes always 0, no 0x3F800000)
// ---------------------------------------------------------------------------
__global__ void mask_detect_kernel(const unsigned int* __restrict__ m) {
    __shared__ int cF, cHi;
    if (threadIdx.x == 0) { cF = 0; cHi = 0; }
    __syncthreads();
    int lf = 0, lh = 0;
    for (int i = threadIdx.x; i < 16384; i += 256) {
        unsigned int w = m[i];
        if (w == 0x3F800000u) lf++;
        else if ((w & 0xFFFFFF00u) != 0u) lh++;
    }
    atomicAdd(&cF, lf);
    atomicAdd(&cHi, lh);
    __syncthreads();
    if (threadIdx.x == 0) {
        if (cF > 16) g_mflag = 2;
        else if (cHi > 16) g_mflag = 0;
        else g_mflag = 1;
    }
}

// Normalize mask into canonical uint8 array. Each thread writes 4 bytes.
__global__ void mask_repack_kernel(const void* __restrict__ mraw) {
    const long long i4 = (long long)blockIdx.x * 256 + threadIdx.x;  // group of 4 elems
    const long long base = i4 * 4;
    if (base >= (long long)N_ACT * N_KEY) return;
    const int flag = g_mflag;
    uchar4 o;
    if (flag == 0) {
        uchar4 b = ((const uchar4*)mraw)[i4];
        o.x = b.x ? 1 : 0; o.y = b.y ? 1 : 0; o.z = b.z ? 1 : 0; o.w = b.w ? 1 : 0;
    } else if (flag == 1) {
        int4 b = ((const int4*)mraw)[i4];
        o.x = b.x ? 1 : 0; o.y = b.y ? 1 : 0; o.z = b.z ? 1 : 0; o.w = b.w ? 1 : 0;
    } else {
        float4 b = ((const float4*)mraw)[i4];
        o.x = (b.x != 0.f) ? 1 : 0; o.y = (b.y != 0.f) ? 1 : 0;
        o.z = (b.z != 0.f) ? 1 : 0; o.w = (b.w != 0.f) ? 1 : 0;
    }
    ((uchar4*)g_mask)[i4] = o;
}

// ---------------------------------------------------------------------------
// Build reduced out-proj weight: wt[dk][c] = mean_h out_w[h*128+dk][c]
// ---------------------------------------------------------------------------
__global__ void build_wt_kernel(const float* __restrict__ ow,
                                const float* __restrict__ ob) {
    int idx = blockIdx.x * 256 + threadIdx.x;
    if (idx < DKH * DMODEL) {
        int dk = idx >> 9, c = idx & 511;
        g_wt[idx] = 0.25f * (ow[dk * DMODEL + c] +
                             ow[(dk + DKH) * DMODEL + c] +
                             ow[(dk + 2 * DKH) * DMODEL + c] +
                             ow[(dk + 3 * DKH) * DMODEL + c]);
    }
    if (idx < DKH) {
        g_bt[idx] = 0.25f * (ob[idx] + ob[idx + DKH] + ob[idx + 2 * DKH] + ob[idx + 3 * DKH]);
    }
}

// ---------------------------------------------------------------------------
// Generic C[n][o] = scale * (X[n][:] . W[o][:] + b[o]); K = 512, X ld = 512.
// 64x64 tile, 256 threads, 4x4 micro.
// ---------------------------------------------------------------------------
__global__ __launch_bounds__(256) void gemm_nt_kernel(
    const float* __restrict__ X, const float* __restrict__ W,
    const float* __restrict__ bias, float* __restrict__ out,
    int ldo, float scale, const int* __restrict__ valid, int fixX)
{
    __shared__ float Xs[64 * 36];
    __shared__ float Ws[64 * 36];
    const int tid = threadIdx.x;
    const int rowBase = blockIdx.y * 64;
    const int colBase = blockIdx.x * 64;
    const int og = tid & 15, ngr = tid >> 4;

    float acc[4][4];
#pragma unroll
    for (int i = 0; i < 4; ++i)
#pragma unroll
        for (int j = 0; j < 4; ++j) acc[i][j] = 0.f;

    for (int kk = 0; kk < 512; kk += 32) {
#pragma unroll
        for (int jj = 0; jj < 2; ++jj) {
            int idx = tid + jj * 256;
            int r = idx >> 3, c4 = (idx & 7) << 2;
            float4 xv = *(const float4*)&X[(rowBase + r) * 512 + kk + c4];
            if (fixX) {
                xv.x = nanfix(xv.x); xv.y = nanfix(xv.y);
                xv.z = nanfix(xv.z); xv.w = nanfix(xv.w);
            }
            *(float4*)&Xs[r * 36 + c4] = xv;
            float4 wv = *(const float4*)&W[(colBase + r) * 512 + kk + c4];
            *(float4*)&Ws[r * 36 + c4] = wv;
        }
        __syncthreads();
#pragma unroll
        for (int k4 = 0; k4 < 32; k4 += 4) {
            float4 xv[4], wv[4];
#pragma unroll
            for (int i = 0; i < 4; ++i) xv[i] = *(const float4*)&Xs[(ngr * 4 + i) * 36 + k4];
#pragma unroll
            for (int j = 0; j < 4; ++j) wv[j] = *(const float4*)&Ws[(og * 4 + j) * 36 + k4];
#pragma unroll
            for (int i = 0; i < 4; ++i)
#pragma unroll
                for (int j = 0; j < 4; ++j) {
                    acc[i][j] = fmaf(xv[i].x, wv[j].x, acc[i][j]);
                    acc[i][j] = fmaf(xv[i].y, wv[j].y, acc[i][j]);
                    acc[i][j] = fmaf(xv[i].z, wv[j].z, acc[i][j]);
                    acc[i][j] = fmaf(xv[i].w, wv[j].w, acc[i][j]);
                }
        }
        __syncthreads();
    }
#pragma unroll
    for (int i = 0; i < 4; ++i) {
        int n = rowBase + ngr * 4 + i;
        float vmul = 1.f;
        if (valid != nullptr && !valid[n]) vmul = 0.f;
#pragma unroll
        for (int j = 0; j < 4; ++j) {
            int o = colBase + og * 4 + j;
            out[n * ldo + o] = vmul * (scale * (acc[i][j] + bias[o]));
        }
    }
}

// ---------------------------------------------------------------------------
// Fused flash-attention + influence accumulators.
// Block: BN=32 actor rows, all 4 heads. 256 threads. Loops over 128 m-tiles.
// ---------------------------------------------------------------------------
__global__ __launch_bounds__(256, 1) void attn_kernel(
    const float* __restrict__ weight,
    float* __restrict__ inf_out)
{
    extern __shared__ float sm[];
    float* Qs   = sm;                         // 32*516
    float* KVs  = Qs + 32 * LDQ;              // 32*516
    float* Ss   = KVs + 32 * LDQ;             // 4*32*33
    float* Bs   = Ss + 4 * 32 * LDSS;         // 32*33
    float* EBs  = Bs + 32 * LDSS;             // 32*33
    float* Alph = EBs + 32 * LDSS;            // 128
    float* Beta = Alph + 128;                 // 32
    float* Zsh  = Beta + 32;                  // 128
    float* CHs  = Zsh + 128;                  // 128
    int*   validS = (int*)(CHs + 128);        // 32

    const int tid = threadIdx.x;
    const int nBase = blockIdx.x * BN;

    // Q tile (persistent)
#pragma unroll
    for (int j = 0; j < 16; ++j) {
        int idx = tid + j * 256;
        int r = idx >> 7, c = (idx & 127) << 2;
        *(float4*)&Qs[r * LDQ + c] = *(const float4*)&g_q[(nBase + r) * DMODEL + c];
    }
    if (tid < 32) validS[tid] = 0;
    __syncthreads();

    float acc[8][8];
#pragma unroll
    for (int i = 0; i < 8; ++i)
#pragma unroll
        for (int k = 0; k < 8; ++k) acc[i][k] = 0.f;

    float Mh = -INFINITY, Zh = 0.f, Ch = 0.f;   // per (n,h), tid<128
    float Mb = -INFINITY, Zb = 0.f;             // per n, tid<32
    int validLoc = 0;

    // role mappings
    const int h1 = tid >> 6, ng1 = (tid >> 3) & 7, mg1 = tid & 7;   // scores
    const int h2 = tid >> 5, n2 = tid & 31;                         // softmax
    const int ng3 = tid & 3, jg3 = tid >> 2;                        // P@V
    const int h3 = jg3 >> 4, d3 = jg3 << 3, n3 = ng3 << 3;
    const int br = tid >> 3, bc = (tid & 7) << 2;                   // bias load

    for (int mt = 0; mt < N_KEY / BM; ++mt) {
        const int mBase = mt * BM;
        // K tile
#pragma unroll
        for (int j = 0; j < 16; ++j) {
            int idx = tid + j * 256;
            int r = idx >> 7, c = (idx & 127) << 2;
            *(float4*)&KVs[r * LDQ + c] = *(const float4*)&g_k[(mBase + r) * DMODEL + c];
        }
        // bias tile (mask + nan_to_num(weight))
        {
            const float4 wv = *(const float4*)&weight[(long long)(nBase + br) * N_KEY + mBase + bc];
            const uchar4 mk = *(const uchar4*)&g_mask[(long long)(nBase + br) * N_KEY + mBase + bc];
            Bs[br * LDSS + bc + 0] = mk.x ? nanfix(wv.x) : NEGV;
            Bs[br * LDSS + bc + 1] = mk.y ? nanfix(wv.y) : NEGV;
            Bs[br * LDSS + bc + 2] = mk.z ? nanfix(wv.z) : NEGV;
            Bs[br * LDSS + bc + 3] = mk.w ? nanfix(wv.w) : NEGV;
            validLoc |= (mk.x | mk.y | mk.z | mk.w);
        }
        __syncthreads();   // S1

        // phase 1: raw scores + bias -> Ss
        {
            float s[4][4];
#pragma unroll
            for (int i = 0; i < 4; ++i)
#pragma unroll
                for (int j = 0; j < 4; ++j) s[i][j] = 0.f;
            const float* qb = Qs + (ng1 * 4) * LDQ + h1 * DKH;
            const float* kb = KVs + (mg1 * 4) * LDQ + h1 * DKH;
#pragma unroll 4
            for (int k = 0; k < DKH; k += 4) {
                float4 qv[4], kv[4];
#pragma unroll
                for (int i = 0; i < 4; ++i) qv[i] = *(const float4*)(qb + i * LDQ + k);
#pragma unroll
                for (int j = 0; j < 4; ++j) kv[j] = *(const float4*)(kb + j * LDQ + k);
#pragma unroll
                for (int i = 0; i < 4; ++i)
#pragma unroll
                    for (int j = 0; j < 4; ++j) {
                        s[i][j] = fmaf(qv[i].x, kv[j].x, s[i][j]);
                        s[i][j] = fmaf(qv[i].y, kv[j].y, s[i][j]);
                        s[i][j] = fmaf(qv[i].z, kv[j].z, s[i][j]);
                        s[i][j] = fmaf(qv[i].w, kv[j].w, s[i][j]);
                    }
            }
#pragma unroll
            for (int i = 0; i < 4; ++i)
#pragma unroll
                for (int j = 0; j < 4; ++j)
                    Ss[h1 * (32 * LDSS) + (ng1 * 4 + i) * LDSS + mg1 * 4 + j] =
                        s[i][j] + Bs[(ng1 * 4 + i) * LDSS + mg1 * 4 + j];
        }
        __syncthreads();   // S2

        // V tile load (all threads) — overlaps with phase 2a
#pragma unroll
        for (int j = 0; j < 16; ++j) {
            int idx = tid + j * 256;
            int r = idx >> 7, c = (idx & 127) << 2;
            *(float4*)&KVs[r * LDQ + c] = *(const float4*)&g_v[(mBase + r) * DMODEL + c];
        }
        // phase 2a: bias softmax online update
        if (tid < 32) {
            const int n = tid;
            float rmax = -INFINITY;
#pragma unroll
            for (int m = 0; m < BM; ++m) rmax = fmaxf(rmax, Bs[n * LDSS + m]);
            float Mn = fmaxf(Mb, rmax);
            float beta = fexp(Mb - Mn);
            float zs = 0.f;
#pragma unroll
            for (int m = 0; m < BM; ++m) {
                float e = fexp(Bs[n * LDSS + m] - Mn);
                EBs[n * LDSS + m] = e;
                zs += e;
            }
            Zb = Zb * beta + zs;
            Beta[n] = beta;
            Mb = Mn;
        }
        __syncthreads();   // S3

        // phase 2b: score softmax online update + cross term
        if (tid < 128) {
            float* srow = &Ss[h2 * (32 * LDSS) + n2 * LDSS];
            float rmax = -INFINITY;
#pragma unroll
            for (int m = 0; m < BM; ++m) rmax = fmaxf(rmax, srow[m]);
            float Mn = fmaxf(Mh, rmax);
            float alpha = fexp(Mh - Mn);
            float zs = 0.f, cs = 0.f;
#pragma unroll
            for (int m = 0; m < BM; ++m) {
                float p = fexp(srow[m] - Mn);
                srow[m] = p;
                zs += p;
                cs = fmaf(EBs[n2 * LDSS + m], p, cs);
            }
            Zh = Zh * alpha + zs;
            Ch = fmaf(Ch * alpha, Beta[n2], cs);
            Mh = Mn;
            Alph[tid] = alpha;
        }
        __syncthreads();   // S4

        // phase 3: ctx accumulate (rescale then P @ V)
        {
#pragma unroll
            for (int i = 0; i < 8; ++i) {
                float al = Alph[h3 * 32 + n3 + i];
#pragma unroll
                for (int k = 0; k < 8; ++k) acc[i][k] *= al;
            }
            const float* prow = &Ss[h3 * (32 * LDSS) + n3 * LDSS];
#pragma unroll 2
            for (int m = 0; m < BM; ++m) {
                const float4 v0 = *(const float4*)&KVs[m * LDQ + d3];
                const float4 v1 = *(const float4*)&KVs[m * LDQ + d3 + 4];
#pragma unroll
                for (int i = 0; i < 8; ++i) {
                    const float p = prow[i * LDSS + m];
                    acc[i][0] = fmaf(p, v0.x, acc[i][0]);
                    acc[i][1] = fmaf(p, v0.y, acc[i][1]);
                    acc[i][2] = fmaf(p, v0.z, acc[i][2]);
                    acc[i][3] = fmaf(p, v0.w, acc[i][3]);
                    acc[i][4] = fmaf(p, v1.x, acc[i][4]);
                    acc[i][5] = fmaf(p, v1.y, acc[i][5]);
                    acc[i][6] = fmaf(p, v1.z, acc[i][6]);
                    acc[i][7] = fmaf(p, v1.w, acc[i][7]);
                }
            }
        }
        __syncthreads();   // S5
    }

    // epilogue
    if (tid < 128) { Zsh[tid] = Zh; CHs[tid] = Ch / Zh; }
    if (validLoc) atomicOr(&validS[br], 1);
    __syncthreads();
    if (tid < 32) {
        const int n = tid;
        float s = CHs[n] + CHs[32 + n] + CHs[64 + n] + CHs[96 + n];
        float v = validS[n] ? (0.25f * s / Zb) : 0.f;
        inf_out[nBase + n] = v;
        g_valid[nBase + n] = validS[n];
    }
    // normalized ctx
#pragma unroll
    for (int i = 0; i < 8; ++i) {
        float inv = 1.f / Zsh[h3 * 32 + n3 + i];
        float4 o0, o1;
        o0.x = acc[i][0] * inv; o0.y = acc[i][1] * inv;
        o0.z = acc[i][2] * inv; o0.w = acc[i][3] * inv;
        o1.x = acc[i][4] * inv; o1.y = acc[i][5] * inv;
        o1.z = acc[i][6] * inv; o1.w = acc[i][7] * inv;
        *(float4*)&g_ctx[(nBase + n3 + i) * DMODEL + d3] = o0;
        *(float4*)&g_ctx[(nBase + n3 + i) * DMODEL + d3 + 4] = o1;
    }
}

// ---------------------------------------------------------------------------
extern "C" void kernel_launch(void* const* d_in, const int* in_sizes, int n_in,
                              void* d_out, int out_size) {
    const float* a      = (const float*)d_in[0];
    const float* bv     = (const float*)d_in[1];
    const void*  mraw   = (const void*)d_in[2];
    const float* weight = (const float*)d_in[3];
    const float* ipw    = (const float*)d_in[4];
    const float* ipb    = (const float*)d_in[5];
    const float* ow     = (const float*)d_in[6];
    const float* ob     = (const float*)d_in[7];
    float* out = (float*)d_out;

    void *pq, *pk, *pv, *pctx;
    cudaGetSymbolAddress(&pq, g_q);
    cudaGetSymbolAddress(&pk, g_k);
    cudaGetSymbolAddress(&pv, g_v);
    cudaGetSymbolAddress(&pctx, g_ctx);
    void *pwt, *pbt, *pvalid;
    cudaGetSymbolAddress(&pwt, g_wt);
    cudaGetSymbolAddress(&pbt, g_bt);
    cudaGetSymbolAddress(&pvalid, g_valid);

    // normalize mask (bool / int32 / float32) into canonical uint8
    mask_detect_kernel<<<1, 256>>>((const unsigned int*)mraw);
    mask_repack_kernel<<<(N_ACT * (long long)N_KEY / 4 + 255) / 256, 256>>>(mraw);

    build_wt_kernel<<<(DKH * DMODEL + 255) / 256, 256>>>(ow, ob);

    const float qscale = 0.08838834764831845f;  // 1/sqrt(128)
    dim3 gProj(8, 64);
    gemm_nt_kernel<<<gProj, 256>>>(a, ipw, ipb, (float*)pq, DMODEL, qscale, nullptr, 1);
    gemm_nt_kernel<<<gProj, 256>>>(bv, ipw + 512 * 512, ipb + 512, (float*)pk, DMODEL, 1.f, nullptr, 1);
    gemm_nt_kernel<<<gProj, 256>>>(bv, ipw + 1024 * 512, ipb + 1024, (float*)pv, DMODEL, 1.f, nullptr, 1);

    const int smemBytes = (2 * 32 * LDQ + 4 * 32 * LDSS + 2 * 32 * LDSS + 128 + 32 + 128 + 128 + 32) * 4;
    cudaFuncSetAttribute(attn_kernel, cudaFuncAttributeMaxDynamicSharedMemorySize, smemBytes);
    attn_kernel<<<N_ACT / BN, 256, smemBytes>>>(weight, out + N_ACT * DKH);

    dim3 gTopic(2, 64);
    gemm_nt_kernel<<<gTopic, 256>>>((const float*)pctx, (const float*)pwt, (const float*)pbt,
                                    out, DKH, 1.f, (const int*)pvalid, 0);
}